// round 2
// baseline (speedup 1.0000x reference)
#include <cuda_runtime.h>

#define B_  64
#define T_  512
#define IN_ 512
#define H_  512
#define G4_ 2048

// ---------------- scratch (device globals; no runtime allocation) ----------
__device__ float g_pre[2][T_][B_][G4_];   // x@Wih^T + bias, [d][t][b][j]  (512 MB)
__device__ float g_h[2][2][B_][H_];       // ping-pong hidden state [phase][d][b][n]
__device__ float g_c[2][B_][H_];          // cell state [d][b][n]

// ---------------- init: scatter enc_h/enc_c into state buffers -------------
__global__ void init_k(const float* __restrict__ enc_h, const float* __restrict__ enc_c) {
    int i = blockIdx.x * blockDim.x + threadIdx.x;   // 0 .. 65535
    int n = i & 511;
    int b = (i >> 9) & 63;
    int d = i >> 15;
    g_h[0][d][b][n] = enc_h[b * 1024 + d * 512 + n];
    g_c[d][b][n]    = enc_c[b * 1024 + d * 512 + n];
}

// ---------------- precompute: pre[d][t][b][j] = x_d[t][b] . Wih_d[j] + bias -
// GEMM: M = T*B = 32768 (m = t*64 + b), N = 2048, K = 512, per direction.
// Tiling: BM=128, BN=64, BK=16, 256 threads, 8x4 register block.
__global__ __launch_bounds__(256) void pre_k(const float* __restrict__ x,
                                             const float* __restrict__ Wf,
                                             const float* __restrict__ bf,
                                             const float* __restrict__ Wb,
                                             const float* __restrict__ bb_) {
    const int d = blockIdx.z;
    const float* __restrict__ W    = d ? Wb  : Wf;
    const float* __restrict__ bias = d ? bb_ : bf;

    __shared__ float As[16][128];   // [k][m]
    __shared__ float Bs[16][64];    // [k][j]

    const int tid = threadIdx.x;
    const int m0  = blockIdx.y * 128;
    const int j0  = blockIdx.x * 64;
    const int tm  = tid >> 4;       // 0..15
    const int tn  = tid & 15;       // 0..15

    float acc[8][4];
#pragma unroll
    for (int i = 0; i < 8; i++)
#pragma unroll
        for (int j = 0; j < 4; j++) acc[i][j] = 0.f;

    for (int k0 = 0; k0 < 512; k0 += 16) {
        // A tile: 128 rows x 16 k = 512 float4, 2 per thread
#pragma unroll
        for (int i = 0; i < 2; i++) {
            int q   = tid + i * 256;
            int row = q >> 2;
            int kq  = (q & 3) * 4;
            int m   = m0 + row;
            int t   = m >> 6;
            int b   = m & 63;
            int tx  = d ? (511 - t) : t;     // backward dir reads flipped time
            float4 v = *(const float4*)(x + ((size_t)b * 512 + tx) * 512 + k0 + kq);
            As[kq + 0][row] = v.x; As[kq + 1][row] = v.y;
            As[kq + 2][row] = v.z; As[kq + 3][row] = v.w;
        }
        // B tile: 64 rows x 16 k = 256 float4, 1 per thread
        {
            int row = tid >> 2;
            int kq  = (tid & 3) * 4;
            float4 v = *(const float4*)(W + (size_t)(j0 + row) * 512 + k0 + kq);
            Bs[kq + 0][row] = v.x; Bs[kq + 1][row] = v.y;
            Bs[kq + 2][row] = v.z; Bs[kq + 3][row] = v.w;
        }
        __syncthreads();

#pragma unroll
        for (int kk = 0; kk < 16; kk++) {
            float a[8], bv[4];
#pragma unroll
            for (int i = 0; i < 8; i++) a[i] = As[kk][tm * 8 + i];
#pragma unroll
            for (int j = 0; j < 4; j++) bv[j] = Bs[kk][tn * 4 + j];
#pragma unroll
            for (int i = 0; i < 8; i++)
#pragma unroll
                for (int j = 0; j < 4; j++) acc[i][j] += a[i] * bv[j];
        }
        __syncthreads();
    }

    float4 bb4 = *(const float4*)(bias + j0 + tn * 4);
#pragma unroll
    for (int i = 0; i < 8; i++) {
        int m = m0 + tm * 8 + i;
        int t = m >> 6;
        int b = m & 63;
        float4 o;
        o.x = acc[i][0] + bb4.x;
        o.y = acc[i][1] + bb4.y;
        o.z = acc[i][2] + bb4.z;
        o.w = acc[i][3] + bb4.w;
        *(float4*)(&g_pre[d][t][b][j0 + tn * 4]) = o;
    }
}

// ---------------- per-timestep recurrence + fused gates ---------------------
// Grid: (64 n-tiles, 2 dirs), 128 threads. Each CTA: 64 batches x 8 n x 4 gates.
// Thread (tb in [0,16), tn in [0,8)): 4 batches x 1 n x 4 gates = 16 accs.
__global__ __launch_bounds__(128) void step_k(const float* __restrict__ Whf,
                                              const float* __restrict__ Whb,
                                              float* __restrict__ out, int t) {
    const int d = blockIdx.y;
    const float* __restrict__ W = d ? Whb : Whf;
    const int tid = threadIdx.x;
    const int tb  = tid >> 3;       // 0..15
    const int tn  = tid & 7;        // 0..7
    const int n0  = blockIdx.x * 8;
    const int n   = n0 + tn;
    const int ph  = t & 1;

    __shared__ float Hs[64][72];    // h chunk, padded rows (288B, 16B-aligned)
    __shared__ float Ws[32][72];    // W chunk: rows = gate*8 + nl

    float acc[4][4];
#pragma unroll
    for (int i = 0; i < 4; i++)
#pragma unroll
        for (int g = 0; g < 4; g++) acc[i][g] = 0.f;

    for (int k0 = 0; k0 < 512; k0 += 64) {
        // h chunk: 64 b x 64 k = 1024 float4, 8 per thread
#pragma unroll
        for (int i = 0; i < 8; i++) {
            int q  = tid + i * 128;
            int b  = q >> 4;
            int kq = (q & 15) * 4;
            float4 v = *(const float4*)(&g_h[ph][d][b][k0 + kq]);
            *(float4*)(&Hs[b][kq]) = v;
        }
        // W chunk: 32 rows x 64 k = 512 float4, 4 per thread
#pragma unroll
        for (int i = 0; i < 4; i++) {
            int q  = tid + i * 128;
            int r  = q >> 4;                       // 0..31
            int kq = (q & 15) * 4;
            int j  = (r >> 3) * 512 + n0 + (r & 7);  // gate*512 + n
            float4 v = *(const float4*)(W + (size_t)j * 512 + k0 + kq);
            *(float4*)(&Ws[r][kq]) = v;
        }
        __syncthreads();

#pragma unroll 4
        for (int kk = 0; kk < 64; kk += 4) {
            float4 h4[4], w4[4];
#pragma unroll
            for (int i = 0; i < 4; i++) h4[i] = *(const float4*)(&Hs[tb * 4 + i][kk]);
#pragma unroll
            for (int g = 0; g < 4; g++) w4[g] = *(const float4*)(&Ws[g * 8 + tn][kk]);
#pragma unroll
            for (int i = 0; i < 4; i++)
#pragma unroll
                for (int g = 0; g < 4; g++) {
                    acc[i][g] += h4[i].x * w4[g].x;
                    acc[i][g] += h4[i].y * w4[g].y;
                    acc[i][g] += h4[i].z * w4[g].z;
                    acc[i][g] += h4[i].w * w4[g].w;
                }
        }
        __syncthreads();
    }

    // fused gate epilogue
    const int tout = d ? (511 - t) : t;
#pragma unroll
    for (int i = 0; i < 4; i++) {
        int b = tb * 4 + i;
        float gi = g_pre[d][t][b][0 * 512 + n] + acc[i][0];
        float gf = g_pre[d][t][b][1 * 512 + n] + acc[i][1];
        float gg = g_pre[d][t][b][2 * 512 + n] + acc[i][2];
        float go = g_pre[d][t][b][3 * 512 + n] + acc[i][3];
        float si = 1.f / (1.f + __expf(-gi));
        float sf = 1.f / (1.f + __expf(-gf));
        float tg = tanhf(gg);
        float so = 1.f / (1.f + __expf(-go));
        float c  = sf * g_c[d][b][n] + si * tg;
        float h  = so * tanhf(c);
        g_c[d][b][n]         = c;
        g_h[ph ^ 1][d][b][n] = h;
        out[((size_t)b * 512 + tout) * 1024 + d * 512 + n] = h;
        if (t == 511) {                          // final h, c sections
            out[33554432 + b * 1024 + d * 512 + n]         = h;
            out[33554432 + 65536 + b * 1024 + d * 512 + n] = c;
        }
    }
}

// ---------------- launch -----------------------------------------------------
extern "C" void kernel_launch(void* const* d_in, const int* in_sizes, int n_in,
                              void* d_out, int out_size) {
    const float* x     = (const float*)d_in[0];
    const float* enc_h = (const float*)d_in[1];
    const float* enc_c = (const float*)d_in[2];
    const float* Wih_f = (const float*)d_in[3];
    const float* Whh_f = (const float*)d_in[4];
    const float* b_f   = (const float*)d_in[5];
    const float* Wih_b = (const float*)d_in[6];
    const float* Whh_b = (const float*)d_in[7];
    const float* b_b   = (const float*)d_in[8];
    float* out = (float*)d_out;

    init_k<<<256, 256>>>(enc_h, enc_c);

    dim3 gA(32, 256, 2);   // (N/64, M/128, dirs)
    pre_k<<<gA, 256>>>(x, Wih_f, b_f, Wih_b, b_b);

    for (int t = 0; t < 512; t++)
        step_k<<<dim3(64, 2), 128>>>(Whh_f, Whh_b, out, t);
}

// round 3
// speedup vs baseline: 1.0803x; 1.0803x over previous
#include <cuda_runtime.h>

#define B_  64
#define T_  512
#define IN_ 512
#define H_  512
#define G4_ 2048

typedef unsigned long long u64;

// ---------------- scratch (device globals; no runtime allocation) ----------
__device__ float g_pre[2][T_][B_][G4_];   // x@Wih^T + bias, [d][t][b][j]  (512 MB)
__device__ float g_h[2][2][B_][H_];       // ping-pong hidden state [phase][d][b][n]
__device__ float g_c[2][B_][H_];          // cell state [d][b][n]

// packed fp32x2 FMA (sm_100+): d = a*b + d on two lanes
__device__ __forceinline__ void ffma2(u64& d, u64 a, u64 b) {
    asm("fma.rn.f32x2 %0, %1, %2, %0;" : "+l"(d) : "l"(a), "l"(b));
}
__device__ __forceinline__ float hsum2(u64 v) {
    float lo, hi;
    asm("mov.b64 {%0,%1}, %2;" : "=f"(lo), "=f"(hi) : "l"(v));
    return lo + hi;
}

// ---------------- init: scatter enc_h/enc_c into state buffers -------------
__global__ void init_k(const float* __restrict__ enc_h, const float* __restrict__ enc_c) {
    int i = blockIdx.x * blockDim.x + threadIdx.x;   // 0 .. 65535
    int n = i & 511;
    int b = (i >> 9) & 63;
    int d = i >> 15;
    g_h[0][d][b][n] = enc_h[b * 1024 + d * 512 + n];
    g_c[d][b][n]    = enc_c[b * 1024 + d * 512 + n];
}

// ---------------- precompute: pre[d][t][b][j] = x_d[t][b] . Wih_d[j] + bias -
// GEMM: M = T*B = 32768 (m = t*64 + b), N = 2048, K = 512, per direction.
// BM=128, BN=64, BK=32, 256 threads, 8x4 register block, f32x2 packed over k.
__global__ __launch_bounds__(256) void pre_k(const float* __restrict__ x,
                                             const float* __restrict__ Wf,
                                             const float* __restrict__ bf,
                                             const float* __restrict__ Wb,
                                             const float* __restrict__ bb_) {
    const int d = blockIdx.z;
    const float* __restrict__ W    = d ? Wb  : Wf;
    const float* __restrict__ bias = d ? bb_ : bf;

    __shared__ float As[128][36];   // [m][k], pad 36
    __shared__ float Bs[64][36];    // [j][k]

    const int tid = threadIdx.x;
    const int m0  = blockIdx.y * 128;
    const int j0  = blockIdx.x * 64;
    const int tm  = tid >> 4;       // 0..15  -> 8 m rows
    const int tn  = tid & 15;       // 0..15  -> 4 j cols

    u64 acc[8][4];
#pragma unroll
    for (int i = 0; i < 8; i++)
#pragma unroll
        for (int j = 0; j < 4; j++) acc[i][j] = 0ull;

    for (int k0 = 0; k0 < 512; k0 += 32) {
        // A tile: 128 rows x 32 k = 1024 float4, 4 per thread
#pragma unroll
        for (int i = 0; i < 4; i++) {
            int q   = tid + i * 256;
            int row = q >> 3;
            int kq  = (q & 7) * 4;
            int m   = m0 + row;
            int t   = m >> 6;
            int b   = m & 63;
            int tx  = d ? (511 - t) : t;
            *(float4*)&As[row][kq] =
                *(const float4*)(x + ((size_t)b * 512 + tx) * 512 + k0 + kq);
        }
        // B tile: 64 rows x 32 k = 512 float4, 2 per thread
#pragma unroll
        for (int i = 0; i < 2; i++) {
            int q   = tid + i * 256;
            int row = q >> 3;
            int kq  = (q & 7) * 4;
            *(float4*)&Bs[row][kq] =
                *(const float4*)(W + (size_t)(j0 + row) * 512 + k0 + kq);
        }
        __syncthreads();

#pragma unroll
        for (int kk = 0; kk < 32; kk += 4) {
            ulonglong2 a2[8], b2[4];
#pragma unroll
            for (int i = 0; i < 8; i++)
                a2[i] = *(const ulonglong2*)&As[tm * 8 + i][kk];
#pragma unroll
            for (int j = 0; j < 4; j++)
                b2[j] = *(const ulonglong2*)&Bs[tn * 4 + j][kk];
#pragma unroll
            for (int i = 0; i < 8; i++)
#pragma unroll
                for (int j = 0; j < 4; j++) {
                    ffma2(acc[i][j], a2[i].x, b2[j].x);
                    ffma2(acc[i][j], a2[i].y, b2[j].y);
                }
        }
        __syncthreads();
    }

    float4 bb4 = *(const float4*)(bias + j0 + tn * 4);
#pragma unroll
    for (int i = 0; i < 8; i++) {
        int m = m0 + tm * 8 + i;
        int t = m >> 6;
        int b = m & 63;
        float4 o;
        o.x = hsum2(acc[i][0]) + bb4.x;
        o.y = hsum2(acc[i][1]) + bb4.y;
        o.z = hsum2(acc[i][2]) + bb4.z;
        o.w = hsum2(acc[i][3]) + bb4.w;
        *(float4*)(&g_pre[d][t][b][j0 + tn * 4]) = o;
    }
}

// ---------------- per-timestep recurrence + fused gates ---------------------
// Grid: (64 n-tiles, 2 dirs) = 128 CTAs, 256 threads (8 warps/SM).
// CTA: 64 batches x 8 n x 4 gates. Thread (tb 0..31, tn 0..7): 2 b x 4 g.
__global__ __launch_bounds__(256) void step_k(const float* __restrict__ Whf,
                                              const float* __restrict__ Whb,
                                              float* __restrict__ out, int t) {
    const int d = blockIdx.y;
    const float* __restrict__ W = d ? Whb : Whf;
    const int tid = threadIdx.x;
    const int tb  = tid >> 3;       // 0..31
    const int tn  = tid & 7;        // 0..7
    const int n0  = blockIdx.x * 8;
    const int n   = n0 + tn;
    const int ph  = t & 1;

    __shared__ float Hs[64][76];    // h chunk [b][k], pad 76 (conflict-free)
    __shared__ float Ws[32][76];    // W chunk [gate*8+nl][k]

    u64 acc[2][4];
#pragma unroll
    for (int i = 0; i < 2; i++)
#pragma unroll
        for (int g = 0; g < 4; g++) acc[i][g] = 0ull;

    for (int k0 = 0; k0 < 512; k0 += 64) {
        // h chunk: 64 b x 64 k = 1024 float4, 4 per thread
#pragma unroll
        for (int i = 0; i < 4; i++) {
            int q  = tid + i * 256;
            int b  = q >> 4;
            int kq = (q & 15) * 4;
            *(float4*)&Hs[b][kq] = *(const float4*)(&g_h[ph][d][b][k0 + kq]);
        }
        // W chunk: 32 rows x 64 k = 512 float4, 2 per thread
#pragma unroll
        for (int i = 0; i < 2; i++) {
            int q  = tid + i * 256;
            int r  = q >> 4;                        // 0..31
            int kq = (q & 15) * 4;
            int j  = (r >> 3) * 512 + n0 + (r & 7); // gate*512 + n
            *(float4*)&Ws[r][kq] = *(const float4*)(W + (size_t)j * 512 + k0 + kq);
        }
        __syncthreads();

#pragma unroll
        for (int kk = 0; kk < 64; kk += 4) {
            ulonglong2 h2[2], w2[4];
#pragma unroll
            for (int i = 0; i < 2; i++)
                h2[i] = *(const ulonglong2*)&Hs[tb * 2 + i][kk];
#pragma unroll
            for (int g = 0; g < 4; g++)
                w2[g] = *(const ulonglong2*)&Ws[g * 8 + tn][kk];
#pragma unroll
            for (int i = 0; i < 2; i++)
#pragma unroll
                for (int g = 0; g < 4; g++) {
                    ffma2(acc[i][g], h2[i].x, w2[g].x);
                    ffma2(acc[i][g], h2[i].y, w2[g].y);
                }
        }
        __syncthreads();
    }

    // fused gate epilogue
    const int tout = d ? (511 - t) : t;
#pragma unroll
    for (int i = 0; i < 2; i++) {
        int b = tb * 2 + i;
        float gi = g_pre[d][t][b][0 * 512 + n] + hsum2(acc[i][0]);
        float gf = g_pre[d][t][b][1 * 512 + n] + hsum2(acc[i][1]);
        float gg = g_pre[d][t][b][2 * 512 + n] + hsum2(acc[i][2]);
        float go = g_pre[d][t][b][3 * 512 + n] + hsum2(acc[i][3]);
        float si = 1.f / (1.f + __expf(-gi));
        float sf = 1.f / (1.f + __expf(-gf));
        float tg = tanhf(gg);
        float so = 1.f / (1.f + __expf(-go));
        float c  = sf * g_c[d][b][n] + si * tg;
        float h  = so * tanhf(c);
        g_c[d][b][n]         = c;
        g_h[ph ^ 1][d][b][n] = h;
        out[((size_t)b * 512 + tout) * 1024 + d * 512 + n] = h;
        if (t == 511) {                          // final h, c sections
            out[33554432 + b * 1024 + d * 512 + n]         = h;
            out[33554432 + 65536 + b * 1024 + d * 512 + n] = c;
        }
    }
}

// ---------------- launch -----------------------------------------------------
extern "C" void kernel_launch(void* const* d_in, const int* in_sizes, int n_in,
                              void* d_out, int out_size) {
    const float* x     = (const float*)d_in[0];
    const float* enc_h = (const float*)d_in[1];
    const float* enc_c = (const float*)d_in[2];
    const float* Wih_f = (const float*)d_in[3];
    const float* Whh_f = (const float*)d_in[4];
    const float* b_f   = (const float*)d_in[5];
    const float* Wih_b = (const float*)d_in[6];
    const float* Whh_b = (const float*)d_in[7];
    const float* b_b   = (const float*)d_in[8];
    float* out = (float*)d_out;

    init_k<<<256, 256>>>(enc_h, enc_c);

    dim3 gA(32, 256, 2);   // (N/64, M/128, dirs)
    pre_k<<<gA, 256>>>(x, Wih_f, b_f, Wih_b, b_b);

    for (int t = 0; t < 512; t++)
        step_k<<<dim3(64, 2), 256>>>(Whh_f, Whh_b, out, t);
}

// round 5
// speedup vs baseline: 1.2226x; 1.1317x over previous
#include <cuda_runtime.h>

#define B_  64
#define T_  512
#define H_  512
#define HS_STRIDE 516                    // 512 + 4 pad
#define NCTA 128
#define SMEM_BYTES ((64 + 32) * HS_STRIDE * 4)   // 198,144 B

typedef unsigned long long u64;

// ---------------- scratch (device globals; no runtime allocation) ----------
__device__ float g_pre[2][T_][B_][2048];   // x@Wih^T + bias, [d][t][b][j]  (512 MB)
__device__ float g_h[2][2][B_][H_];        // ping-pong hidden state [phase][d][b][n]
__device__ unsigned g_bar;                 // grid barrier counter

// packed fp32x2 FMA (sm_100+)
__device__ __forceinline__ void ffma2(u64& d, u64 a, u64 b) {
    asm("fma.rn.f32x2 %0, %1, %2, %0;" : "+l"(d) : "l"(a), "l"(b));
}
__device__ __forceinline__ float hsum2(u64 v) {
    float lo, hi;
    asm("mov.b64 {%0,%1}, %2;" : "=f"(lo), "=f"(hi) : "l"(v));
    return lo + hi;
}
__device__ __forceinline__ void cp_async16(unsigned saddr, const void* gptr) {
    asm volatile("cp.async.cg.shared.global [%0], [%1], 16;" :: "r"(saddr), "l"(gptr));
}
__device__ __forceinline__ void cp_commit() { asm volatile("cp.async.commit_group;"); }
__device__ __forceinline__ void cp_wait0()  { asm volatile("cp.async.wait_group 0;" ::: "memory"); }

// ---------------- init: h0 scatter + barrier reset --------------------------
__global__ void init_k(const float* __restrict__ enc_h) {
    int i = blockIdx.x * blockDim.x + threadIdx.x;   // 0 .. 65535
    int n = i & 511;
    int b = (i >> 9) & 63;
    int d = i >> 15;
    g_h[0][d][b][n] = enc_h[b * 1024 + d * 512 + n];
    if (i == 0) g_bar = 0;
}

// ---------------- precompute: pre[d][t][b][j] = x_d[t][b] . Wih_d[j] + bias -
__global__ __launch_bounds__(256) void pre_k(const float* __restrict__ x,
                                             const float* __restrict__ Wf,
                                             const float* __restrict__ bf,
                                             const float* __restrict__ Wb,
                                             const float* __restrict__ bb_) {
    const int d = blockIdx.z;
    const float* __restrict__ W    = d ? Wb  : Wf;
    const float* __restrict__ bias = d ? bb_ : bf;

    __shared__ float As[128][36];
    __shared__ float Bs[64][36];

    const int tid = threadIdx.x;
    const int m0  = blockIdx.y * 128;
    const int j0  = blockIdx.x * 64;
    const int tm  = tid >> 4;
    const int tn  = tid & 15;

    u64 acc[8][4];
#pragma unroll
    for (int i = 0; i < 8; i++)
#pragma unroll
        for (int j = 0; j < 4; j++) acc[i][j] = 0ull;

    for (int k0 = 0; k0 < 512; k0 += 32) {
#pragma unroll
        for (int i = 0; i < 4; i++) {
            int q   = tid + i * 256;
            int row = q >> 3;
            int kq  = (q & 7) * 4;
            int m   = m0 + row;
            int t   = m >> 6;
            int b   = m & 63;
            int tx  = d ? (511 - t) : t;
            *(float4*)&As[row][kq] =
                *(const float4*)(x + ((size_t)b * 512 + tx) * 512 + k0 + kq);
        }
#pragma unroll
        for (int i = 0; i < 2; i++) {
            int q   = tid + i * 256;
            int row = q >> 3;
            int kq  = (q & 7) * 4;
            *(float4*)&Bs[row][kq] =
                *(const float4*)(W + (size_t)(j0 + row) * 512 + k0 + kq);
        }
        __syncthreads();

#pragma unroll
        for (int kk = 0; kk < 32; kk += 4) {
            ulonglong2 a2[8], b2[4];
#pragma unroll
            for (int i = 0; i < 8; i++)
                a2[i] = *(const ulonglong2*)&As[tm * 8 + i][kk];
#pragma unroll
            for (int j = 0; j < 4; j++)
                b2[j] = *(const ulonglong2*)&Bs[tn * 4 + j][kk];
#pragma unroll
            for (int i = 0; i < 8; i++)
#pragma unroll
                for (int j = 0; j < 4; j++) {
                    ffma2(acc[i][j], a2[i].x, b2[j].x);
                    ffma2(acc[i][j], a2[i].y, b2[j].y);
                }
        }
        __syncthreads();
    }

    float4 bb4 = *(const float4*)(bias + j0 + tn * 4);
#pragma unroll
    for (int i = 0; i < 8; i++) {
        int m = m0 + tm * 8 + i;
        int t = m >> 6;
        int b = m & 63;
        float4 o;
        o.x = hsum2(acc[i][0]) + bb4.x;
        o.y = hsum2(acc[i][1]) + bb4.y;
        o.z = hsum2(acc[i][2]) + bb4.z;
        o.w = hsum2(acc[i][3]) + bb4.w;
        *(float4*)(&g_pre[d][t][b][j0 + tn * 4]) = o;
    }
}

// ---------------- persistent recurrence kernel -------------------------------
// 128 CTAs (1/SM, wave-1 co-resident), 256 threads. CTA = (d, 8-wide n slice):
// owns 32 W rows (4 gates x 8 n) in smem for all 512 steps.
// Thread (tb 0..31, tn 0..7): 2 batches x 4 gates; c kept in registers.
__global__ __launch_bounds__(256, 1) void persist_k(const float* __restrict__ Whf,
                                                    const float* __restrict__ Whb,
                                                    const float* __restrict__ enc_c,
                                                    float* __restrict__ out) {
    extern __shared__ float smem[];
    float* Hs = smem;                       // [64][HS_STRIDE]
    float* Ws = smem + 64 * HS_STRIDE;      // [32][HS_STRIDE]
    const unsigned hs_base = (unsigned)__cvta_generic_to_shared(Hs);

    const int d   = blockIdx.x >> 6;
    const int n0  = (blockIdx.x & 63) * 8;
    const int tid = threadIdx.x;
    const int tb  = tid >> 3;               // 0..31
    const int tn  = tid & 7;                // 0..7
    const int n   = n0 + tn;
    const float* __restrict__ W = d ? Whb : Whf;

    // ---- load resident W tile: 32 rows x 512 k = 4096 float4, 16/thread ----
#pragma unroll
    for (int i = 0; i < 16; i++) {
        int q  = tid + i * 256;
        int r  = q >> 7;                    // 0..31
        int kq = (q & 127) * 4;
        int j  = (r >> 3) * 512 + n0 + (r & 7);   // gate*512 + n
        *(float4*)&Ws[r * HS_STRIDE + kq] = *(const float4*)(W + (size_t)j * 512 + kq);
    }

    // ---- c state in registers ----
    float c_reg[2];
#pragma unroll
    for (int i = 0; i < 2; i++)
        c_reg[i] = enc_c[(tb * 2 + i) * 1024 + d * 512 + n];

    const float* hrow0 = Hs + (tb * 2)     * HS_STRIDE;
    const float* hrow1 = Hs + (tb * 2 + 1) * HS_STRIDE;
    const float* wrow0 = Ws + (0 * 8 + tn) * HS_STRIDE;
    const float* wrow1 = Ws + (1 * 8 + tn) * HS_STRIDE;
    const float* wrow2 = Ws + (2 * 8 + tn) * HS_STRIDE;
    const float* wrow3 = Ws + (3 * 8 + tn) * HS_STRIDE;

    for (int t = 0; t < 512; t++) {
        const int ph = t & 1;

        // ---- stage full h[d] (64x512) into smem via cp.async (L2-coherent) ----
#pragma unroll
        for (int i = 0; i < 32; i++) {
            int q  = tid + i * 256;
            int b  = q >> 7;
            int kq = (q & 127) * 4;
            cp_async16(hs_base + (unsigned)(b * HS_STRIDE + kq) * 4,
                       &g_h[ph][d][b][kq]);
        }
        cp_commit();

        // ---- prefetch pre-activations for the epilogue (overlapped) ----
        float pre_r[2][4];
#pragma unroll
        for (int i = 0; i < 2; i++)
#pragma unroll
            for (int g = 0; g < 4; g++)
                pre_r[i][g] = g_pre[d][t][tb * 2 + i][g * 512 + n];

        cp_wait0();
        __syncthreads();

        // ---- barrier-free compute, manual register double-buffer ----
        u64 acc[2][4];
#pragma unroll
        for (int i = 0; i < 2; i++)
#pragma unroll
            for (int g = 0; g < 4; g++) acc[i][g] = 0ull;

        ulonglong2 ch0 = *(const ulonglong2*)(hrow0);
        ulonglong2 ch1 = *(const ulonglong2*)(hrow1);
        ulonglong2 cw0 = *(const ulonglong2*)(wrow0);
        ulonglong2 cw1 = *(const ulonglong2*)(wrow1);
        ulonglong2 cw2 = *(const ulonglong2*)(wrow2);
        ulonglong2 cw3 = *(const ulonglong2*)(wrow3);

#pragma unroll 8
        for (int kk = 0; kk < 512; kk += 4) {
            ulonglong2 nh0, nh1, nw0, nw1, nw2, nw3;
            if (kk + 4 < 512) {
                nh0 = *(const ulonglong2*)(hrow0 + kk + 4);
                nh1 = *(const ulonglong2*)(hrow1 + kk + 4);
                nw0 = *(const ulonglong2*)(wrow0 + kk + 4);
                nw1 = *(const ulonglong2*)(wrow1 + kk + 4);
                nw2 = *(const ulonglong2*)(wrow2 + kk + 4);
                nw3 = *(const ulonglong2*)(wrow3 + kk + 4);
            }
            ffma2(acc[0][0], ch0.x, cw0.x); ffma2(acc[0][0], ch0.y, cw0.y);
            ffma2(acc[0][1], ch0.x, cw1.x); ffma2(acc[0][1], ch0.y, cw1.y);
            ffma2(acc[0][2], ch0.x, cw2.x); ffma2(acc[0][2], ch0.y, cw2.y);
            ffma2(acc[0][3], ch0.x, cw3.x); ffma2(acc[0][3], ch0.y, cw3.y);
            ffma2(acc[1][0], ch1.x, cw0.x); ffma2(acc[1][0], ch1.y, cw0.y);
            ffma2(acc[1][1], ch1.x, cw1.x); ffma2(acc[1][1], ch1.y, cw1.y);
            ffma2(acc[1][2], ch1.x, cw2.x); ffma2(acc[1][2], ch1.y, cw2.y);
            ffma2(acc[1][3], ch1.x, cw3.x); ffma2(acc[1][3], ch1.y, cw3.y);
            ch0 = nh0; ch1 = nh1;
            cw0 = nw0; cw1 = nw1; cw2 = nw2; cw3 = nw3;
        }

        // ---- fused gate epilogue ----
        const int tout = d ? (511 - t) : t;
#pragma unroll
        for (int i = 0; i < 2; i++) {
            int b = tb * 2 + i;
            float gi = pre_r[i][0] + hsum2(acc[i][0]);
            float gf = pre_r[i][1] + hsum2(acc[i][1]);
            float gg = pre_r[i][2] + hsum2(acc[i][2]);
            float go = pre_r[i][3] + hsum2(acc[i][3]);
            float si = 1.f / (1.f + __expf(-gi));
            float sf = 1.f / (1.f + __expf(-gf));
            float tg = tanhf(gg);
            float so = 1.f / (1.f + __expf(-go));
            float c  = sf * c_reg[i] + si * tg;
            float h  = so * tanhf(c);
            c_reg[i] = c;
            g_h[ph ^ 1][d][b][n] = h;
            out[((size_t)b * 512 + tout) * 1024 + d * 512 + n] = h;
            if (t == 511) {
                out[33554432 + b * 1024 + d * 512 + n]         = h;
                out[33554432 + 65536 + b * 1024 + d * 512 + n] = c;
            }
        }

        // ---- grid barrier (skip after final step) ----
        if (t < 511) {
            __threadfence();
            __syncthreads();
            if (tid == 0) {
                atomicAdd(&g_bar, 1u);
                unsigned target = (unsigned)NCTA * (t + 1);
                unsigned v;
                do {
                    asm volatile("ld.global.acquire.gpu.u32 %0, [%1];"
                                 : "=r"(v) : "l"(&g_bar));
                } while (v < target);
            }
            __syncthreads();
        }
    }
}

// ---------------- launch -----------------------------------------------------
extern "C" void kernel_launch(void* const* d_in, const int* in_sizes, int n_in,
                              void* d_out, int out_size) {
    const float* x     = (const float*)d_in[0];
    const float* enc_h = (const float*)d_in[1];
    const float* enc_c = (const float*)d_in[2];
    const float* Wih_f = (const float*)d_in[3];
    const float* Whh_f = (const float*)d_in[4];
    const float* b_f   = (const float*)d_in[5];
    const float* Wih_b = (const float*)d_in[6];
    const float* Whh_b = (const float*)d_in[7];
    const float* b_b   = (const float*)d_in[8];
    float* out = (float*)d_out;

    cudaFuncSetAttribute(persist_k, cudaFuncAttributeMaxDynamicSharedMemorySize,
                         SMEM_BYTES);

    init_k<<<256, 256>>>(enc_h);

    dim3 gA(32, 256, 2);   // (N/64, M/128, dirs)
    pre_k<<<gA, 256>>>(x, Wih_f, b_f, Wih_b, b_b);

    persist_k<<<NCTA, 256, SMEM_BYTES>>>(Whh_f, Whh_b, enc_c, out);
}

// round 6
// speedup vs baseline: 1.2318x; 1.0075x over previous
#include <cuda_runtime.h>

#define B_  64
#define T_  512
#define H_  512
#define HS_STRIDE 516                    // 512 + 4 pad
#define NCTA 128
#define SMEM_BYTES ((64 + 32) * HS_STRIDE * 4)   // 198,144 B

typedef unsigned long long u64;

// ---------------- scratch (device globals; no runtime allocation) ----------
__device__ float g_pre[2][T_][B_][2048];   // x@Wih^T + bias  (512 MB)
__device__ float g_h[2][2][B_][H_];        // ping-pong hidden state [phase][d][b][n]
__device__ unsigned g_cnt[2 * 32];         // per-dir arrival counter (padded lines)
__device__ unsigned g_flag[2 * 32];        // per-dir epoch flag (padded lines)

// packed fp32x2 FMA (sm_100+)
__device__ __forceinline__ void ffma2(u64& d, u64 a, u64 b) {
    asm("fma.rn.f32x2 %0, %1, %2, %0;" : "+l"(d) : "l"(a), "l"(b));
}
__device__ __forceinline__ float hsum2(u64 v) {
    float lo, hi;
    asm("mov.b64 {%0,%1}, %2;" : "=f"(lo), "=f"(hi) : "l"(v));
    return lo + hi;
}
__device__ __forceinline__ void cp_async16(unsigned saddr, const void* gptr) {
    asm volatile("cp.async.cg.shared.global [%0], [%1], 16;" :: "r"(saddr), "l"(gptr));
}
__device__ __forceinline__ void cp_commit() { asm volatile("cp.async.commit_group;"); }
__device__ __forceinline__ void cp_wait0()  { asm volatile("cp.async.wait_group 0;" ::: "memory"); }
__device__ __forceinline__ unsigned ld_acq(const unsigned* p) {
    unsigned v;
    asm volatile("ld.global.acquire.gpu.u32 %0, [%1];" : "=r"(v) : "l"(p));
    return v;
}
__device__ __forceinline__ void st_rel(unsigned* p, unsigned v) {
    asm volatile("st.global.release.gpu.u32 [%0], %1;" :: "l"(p), "r"(v));
}
__device__ __forceinline__ float tanh_fast(float x) {
    float y;
    asm("tanh.approx.f32 %0, %1;" : "=f"(y) : "f"(x));
    return y;
}
__device__ __forceinline__ float sigmoid_fast(float x) {   // 0.5*tanh(0.5x)+0.5
    return fmaf(0.5f, tanh_fast(0.5f * x), 0.5f);
}

// ---------------- dummy (profiler slot alignment) ---------------------------
__global__ void dummy_k() {}

// ---------------- init: h0 scatter -------------------------------------------
__global__ void init_k(const float* __restrict__ enc_h) {
    int i = blockIdx.x * blockDim.x + threadIdx.x;   // 0 .. 65535
    int n = i & 511;
    int b = (i >> 9) & 63;
    int d = i >> 15;
    g_h[0][d][b][n] = enc_h[b * 1024 + d * 512 + n];
}

// ---------------- precompute GEMM --------------------------------------------
__global__ __launch_bounds__(256) void pre_k(const float* __restrict__ x,
                                             const float* __restrict__ Wf,
                                             const float* __restrict__ bf,
                                             const float* __restrict__ Wb,
                                             const float* __restrict__ bb_) {
    const int d = blockIdx.z;
    const float* __restrict__ W    = d ? Wb  : Wf;
    const float* __restrict__ bias = d ? bb_ : bf;

    __shared__ float As[128][36];
    __shared__ float Bs[64][36];

    const int tid = threadIdx.x;
    const int m0  = blockIdx.y * 128;
    const int j0  = blockIdx.x * 64;
    const int tm  = tid >> 4;
    const int tn  = tid & 15;

    u64 acc[8][4];
#pragma unroll
    for (int i = 0; i < 8; i++)
#pragma unroll
        for (int j = 0; j < 4; j++) acc[i][j] = 0ull;

    for (int k0 = 0; k0 < 512; k0 += 32) {
#pragma unroll
        for (int i = 0; i < 4; i++) {
            int q   = tid + i * 256;
            int row = q >> 3;
            int kq  = (q & 7) * 4;
            int m   = m0 + row;
            int t   = m >> 6;
            int b   = m & 63;
            int tx  = d ? (511 - t) : t;
            *(float4*)&As[row][kq] =
                *(const float4*)(x + ((size_t)b * 512 + tx) * 512 + k0 + kq);
        }
#pragma unroll
        for (int i = 0; i < 2; i++) {
            int q   = tid + i * 256;
            int row = q >> 3;
            int kq  = (q & 7) * 4;
            *(float4*)&Bs[row][kq] =
                *(const float4*)(W + (size_t)(j0 + row) * 512 + k0 + kq);
        }
        __syncthreads();

#pragma unroll
        for (int kk = 0; kk < 32; kk += 4) {
            ulonglong2 a2[8], b2[4];
#pragma unroll
            for (int i = 0; i < 8; i++)
                a2[i] = *(const ulonglong2*)&As[tm * 8 + i][kk];
#pragma unroll
            for (int j = 0; j < 4; j++)
                b2[j] = *(const ulonglong2*)&Bs[tn * 4 + j][kk];
#pragma unroll
            for (int i = 0; i < 8; i++)
#pragma unroll
                for (int j = 0; j < 4; j++) {
                    ffma2(acc[i][j], a2[i].x, b2[j].x);
                    ffma2(acc[i][j], a2[i].y, b2[j].y);
                }
        }
        __syncthreads();
    }

    float4 bb4 = *(const float4*)(bias + j0 + tn * 4);
#pragma unroll
    for (int i = 0; i < 8; i++) {
        int m = m0 + tm * 8 + i;
        int t = m >> 6;
        int b = m & 63;
        float4 o;
        o.x = hsum2(acc[i][0]) + bb4.x;
        o.y = hsum2(acc[i][1]) + bb4.y;
        o.z = hsum2(acc[i][2]) + bb4.z;
        o.w = hsum2(acc[i][3]) + bb4.w;
        *(float4*)(&g_pre[d][t][b][j0 + tn * 4]) = o;
    }
}

// ---------------- persistent recurrence kernel -------------------------------
__global__ __launch_bounds__(256, 1) void persist_k(const float* __restrict__ Whf,
                                                    const float* __restrict__ Whb,
                                                    const float* __restrict__ enc_c,
                                                    float* __restrict__ out) {
    extern __shared__ float smem[];
    float* Hs = smem;                       // [64][HS_STRIDE]
    float* Ws = smem + 64 * HS_STRIDE;      // [32][HS_STRIDE]
    const unsigned hs_base = (unsigned)__cvta_generic_to_shared(Hs);

    const int d   = blockIdx.x >> 6;
    const int n0  = (blockIdx.x & 63) * 8;
    const int tid = threadIdx.x;
    const int tb  = tid >> 3;               // 0..31
    const int tn  = tid & 7;                // 0..7
    const int n   = n0 + tn;
    const float* __restrict__ W = d ? Whb : Whf;

    unsigned* cnt  = &g_cnt[d * 32];
    unsigned* flag = &g_flag[d * 32];
    unsigned  base = 0;
    if (tid == 0) base = *flag;             // monotonic epoch base (replay-safe)

    // ---- resident W tile: 32 rows x 512 k ----
#pragma unroll
    for (int i = 0; i < 16; i++) {
        int q  = tid + i * 256;
        int r  = q >> 7;
        int kq = (q & 127) * 4;
        int j  = (r >> 3) * 512 + n0 + (r & 7);
        *(float4*)&Ws[r * HS_STRIDE + kq] = *(const float4*)(W + (size_t)j * 512 + kq);
    }

    float c_reg[2];
#pragma unroll
    for (int i = 0; i < 2; i++)
        c_reg[i] = enc_c[(tb * 2 + i) * 1024 + d * 512 + n];

    const float* hrow0 = Hs + (tb * 2)     * HS_STRIDE;
    const float* hrow1 = Hs + (tb * 2 + 1) * HS_STRIDE;
    const float* wr[4] = { Ws + (0 * 8 + tn) * HS_STRIDE, Ws + (1 * 8 + tn) * HS_STRIDE,
                           Ws + (2 * 8 + tn) * HS_STRIDE, Ws + (3 * 8 + tn) * HS_STRIDE };

    for (int t = 0; t < 512; t++) {
        const int ph = t & 1;

        // ---- stage h[d] (64x512) into smem via cp.async ----
#pragma unroll
        for (int i = 0; i < 32; i++) {
            int q  = tid + i * 256;
            int b  = q >> 7;
            int kq = (q & 127) * 4;
            cp_async16(hs_base + (unsigned)(b * HS_STRIDE + kq) * 4,
                       &g_h[ph][d][b][kq]);
        }
        cp_commit();

        // ---- epilogue operand prefetch (streaming loads) ----
        float pre_r[2][4];
#pragma unroll
        for (int i = 0; i < 2; i++)
#pragma unroll
            for (int g = 0; g < 4; g++)
                pre_r[i][g] = __ldcs(&g_pre[d][t][tb * 2 + i][g * 512 + n]);

        cp_wait0();
        __syncthreads();

        // ---- compute: 8-k blocks, prefetch 1 block (8k = 32 FFMA2) ahead ----
        u64 acc[2][4];
#pragma unroll
        for (int i = 0; i < 2; i++)
#pragma unroll
            for (int g = 0; g < 4; g++) acc[i][g] = 0ull;

        ulonglong2 ch[2][2], cw[4][2];
#pragma unroll
        for (int u = 0; u < 2; u++) {
            ch[0][u] = *(const ulonglong2*)(hrow0 + u * 4);
            ch[1][u] = *(const ulonglong2*)(hrow1 + u * 4);
#pragma unroll
            for (int g = 0; g < 4; g++)
                cw[g][u] = *(const ulonglong2*)(wr[g] + u * 4);
        }

#pragma unroll 4
        for (int kk = 0; kk < 512; kk += 8) {
            ulonglong2 nh[2][2], nw[4][2];
            if (kk + 8 < 512) {
#pragma unroll
                for (int u = 0; u < 2; u++) {
                    nh[0][u] = *(const ulonglong2*)(hrow0 + kk + 8 + u * 4);
                    nh[1][u] = *(const ulonglong2*)(hrow1 + kk + 8 + u * 4);
#pragma unroll
                    for (int g = 0; g < 4; g++)
                        nw[g][u] = *(const ulonglong2*)(wr[g] + kk + 8 + u * 4);
                }
            }
#pragma unroll
            for (int u = 0; u < 2; u++)
#pragma unroll
                for (int g = 0; g < 4; g++) {
                    ffma2(acc[0][g], ch[0][u].x, cw[g][u].x);
                    ffma2(acc[0][g], ch[0][u].y, cw[g][u].y);
                    ffma2(acc[1][g], ch[1][u].x, cw[g][u].x);
                    ffma2(acc[1][g], ch[1][u].y, cw[g][u].y);
                }
#pragma unroll
            for (int u = 0; u < 2; u++) {
                ch[0][u] = nh[0][u]; ch[1][u] = nh[1][u];
#pragma unroll
                for (int g = 0; g < 4; g++) cw[g][u] = nw[g][u];
            }
        }

        // ---- fused gate epilogue ----
        const int tout = d ? (511 - t) : t;
#pragma unroll
        for (int i = 0; i < 2; i++) {
            int b = tb * 2 + i;
            float gi = pre_r[i][0] + hsum2(acc[i][0]);
            float gf = pre_r[i][1] + hsum2(acc[i][1]);
            float gg = pre_r[i][2] + hsum2(acc[i][2]);
            float go = pre_r[i][3] + hsum2(acc[i][3]);
            float si = sigmoid_fast(gi);
            float sf = sigmoid_fast(gf);
            float tg = tanh_fast(gg);
            float so = sigmoid_fast(go);
            float c  = sf * c_reg[i] + si * tg;
            float h  = so * tanh_fast(c);
            c_reg[i] = c;
            g_h[ph ^ 1][d][b][n] = h;
            __stcs(&out[((size_t)b * 512 + tout) * 1024 + d * 512 + n], h);
            if (t == 511) {
                __stcs(&out[33554432 + b * 1024 + d * 512 + n], h);
                __stcs(&out[33554432 + 65536 + b * 1024 + d * 512 + n], c);
            }
        }

        // ---- per-direction barrier (monotonic epochs, release-flag) ----
        if (t < 511) {
            __threadfence();
            __syncthreads();
            if (tid == 0) {
                unsigned target = base + (unsigned)(t + 1);
                unsigned ticket = atomicAdd(cnt, 1u);
                if ((ticket & 63u) == 63u) {
                    st_rel(flag, target);           // last arriver publishes
                } else {
                    while (ld_acq(flag) < target) __nanosleep(64);
                }
            }
            __syncthreads();
        }
    }
}

// ---------------- launch -----------------------------------------------------
extern "C" void kernel_launch(void* const* d_in, const int* in_sizes, int n_in,
                              void* d_out, int out_size) {
    const float* x     = (const float*)d_in[0];
    const float* enc_h = (const float*)d_in[1];
    const float* enc_c = (const float*)d_in[2];
    const float* Wih_f = (const float*)d_in[3];
    const float* Whh_f = (const float*)d_in[4];
    const float* b_f   = (const float*)d_in[5];
    const float* Wih_b = (const float*)d_in[6];
    const float* Whh_b = (const float*)d_in[7];
    const float* b_b   = (const float*)d_in[8];
    float* out = (float*)d_out;

    cudaFuncSetAttribute(persist_k, cudaFuncAttributeMaxDynamicSharedMemorySize,
                         SMEM_BYTES);

    dummy_k<<<1, 32>>>();                  // profiler slot alignment
    init_k<<<256, 256>>>(enc_h);

    dim3 gA(32, 256, 2);
    pre_k<<<gA, 256>>>(x, Wih_f, b_f, Wih_b, b_b);

    persist_k<<<NCTA, 256, SMEM_BYTES>>>(Whh_f, Whh_b, enc_c, out);
}

// round 8
// speedup vs baseline: 1.6635x; 1.3504x over previous
#include <cuda_runtime.h>
#include <cuda_bf16.h>
#include <cstdint>

#define B_  64
#define T_  512
#define H_  512
#define NCTA 128

// persist smem layout (bf16, padded rows: 520 = 512+8 -> conflict-free ldmatrix)
#define HB 520
#define SM_HH 0
#define SM_HL (64 * HB * 2)                 // 66560
#define SM_WH (2 * 64 * HB * 2)             // 133120
#define SM_WL (SM_WH + 32 * HB * 2)         // 166400
#define PERSIST_SMEM (SM_WL + 32 * HB * 2)  // 199680

typedef unsigned long long u64;

// ---------------- scratch (device globals; no runtime allocation) ----------
__device__ float g_pre[2][T_][B_][2048];          // x@Wih^T + bias  (512 MB)
__device__ __nv_bfloat16 g_hh[2][2][B_][H_];      // h hi, ping-pong [phase][d][b][n]
__device__ __nv_bfloat16 g_hl[2][2][B_][H_];      // h lo
__device__ unsigned g_cnt[2 * 32];                // per-dir arrival counter
__device__ unsigned g_flag[2 * 32];               // per-dir epoch flag

// ---------------- helpers -----------------------------------------------------
__device__ __forceinline__ void ffma2(u64& d, u64 a, u64 b) {
    asm("fma.rn.f32x2 %0, %1, %2, %0;" : "+l"(d) : "l"(a), "l"(b));
}
__device__ __forceinline__ float hsum2(u64 v) {
    float lo, hi;
    asm("mov.b64 {%0,%1}, %2;" : "=f"(lo), "=f"(hi) : "l"(v));
    return lo + hi;
}
__device__ __forceinline__ void cp_async16(unsigned saddr, const void* gptr) {
    asm volatile("cp.async.cg.shared.global [%0], [%1], 16;" :: "r"(saddr), "l"(gptr));
}
__device__ __forceinline__ void cp_commit() { asm volatile("cp.async.commit_group;"); }
__device__ __forceinline__ void cp_wait0()  { asm volatile("cp.async.wait_group 0;" ::: "memory"); }
__device__ __forceinline__ unsigned ld_acq(const unsigned* p) {
    unsigned v;
    asm volatile("ld.global.acquire.gpu.u32 %0, [%1];" : "=r"(v) : "l"(p));
    return v;
}
__device__ __forceinline__ void st_rel(unsigned* p, unsigned v) {
    asm volatile("st.global.release.gpu.u32 [%0], %1;" :: "l"(p), "r"(v));
}
__device__ __forceinline__ float tanh_fast(float x) {
    float y;
    asm("tanh.approx.f32 %0, %1;" : "=f"(y) : "f"(x));
    return y;
}
__device__ __forceinline__ float sigmoid_fast(float x) {
    return fmaf(0.5f, tanh_fast(0.5f * x), 0.5f);
}
__device__ __forceinline__ void ldsm4(uint32_t r[4], uint32_t addr) {
    asm volatile("ldmatrix.sync.aligned.m8n8.x4.shared.b16 {%0,%1,%2,%3}, [%4];"
                 : "=r"(r[0]), "=r"(r[1]), "=r"(r[2]), "=r"(r[3]) : "r"(addr));
}
__device__ __forceinline__ void mma16816(float d[4], const uint32_t a[4],
                                         uint32_t b0, uint32_t b1) {
    asm volatile(
        "mma.sync.aligned.m16n8k16.row.col.f32.bf16.bf16.f32 "
        "{%0,%1,%2,%3}, {%4,%5,%6,%7}, {%8,%9}, {%0,%1,%2,%3};"
        : "+f"(d[0]), "+f"(d[1]), "+f"(d[2]), "+f"(d[3])
        : "r"(a[0]), "r"(a[1]), "r"(a[2]), "r"(a[3]), "r"(b0), "r"(b1));
}
__device__ __forceinline__ void split_bf16(float v, __nv_bfloat16& h, __nv_bfloat16& l) {
    h = __float2bfloat16_rn(v);
    l = __float2bfloat16_rn(v - __bfloat162float(h));
}

// ---------------- dummy (profiler slot alignment: slot5 = persist_k) --------
__global__ void dummy_k() {}

// ---------------- init: h0 split-scatter -------------------------------------
__global__ void init_k(const float* __restrict__ enc_h) {
    int i = blockIdx.x * blockDim.x + threadIdx.x;   // 0 .. 65535
    int n = i & 511;
    int b = (i >> 9) & 63;
    int d = i >> 15;
    __nv_bfloat16 h, l;
    split_bf16(enc_h[b * 1024 + d * 512 + n], h, l);
    g_hh[0][d][b][n] = h;
    g_hl[0][d][b][n] = l;
}

// ---------------- precompute GEMM (fp32 FFMA2, proven) -----------------------
__global__ __launch_bounds__(256) void pre_k(const float* __restrict__ x,
                                             const float* __restrict__ Wf,
                                             const float* __restrict__ bf,
                                             const float* __restrict__ Wb,
                                             const float* __restrict__ bb_) {
    const int d = blockIdx.z;
    const float* __restrict__ W    = d ? Wb  : Wf;
    const float* __restrict__ bias = d ? bb_ : bf;

    __shared__ float As[128][36];
    __shared__ float Bs[64][36];

    const int tid = threadIdx.x;
    const int m0  = blockIdx.y * 128;
    const int j0  = blockIdx.x * 64;
    const int tm  = tid >> 4;
    const int tn  = tid & 15;

    u64 acc[8][4];
#pragma unroll
    for (int i = 0; i < 8; i++)
#pragma unroll
        for (int j = 0; j < 4; j++) acc[i][j] = 0ull;

    for (int k0 = 0; k0 < 512; k0 += 32) {
#pragma unroll
        for (int i = 0; i < 4; i++) {
            int q   = tid + i * 256;
            int row = q >> 3;
            int kq  = (q & 7) * 4;
            int m   = m0 + row;
            int t   = m >> 6;
            int b   = m & 63;
            int tx  = d ? (511 - t) : t;
            *(float4*)&As[row][kq] =
                *(const float4*)(x + ((size_t)b * 512 + tx) * 512 + k0 + kq);
        }
#pragma unroll
        for (int i = 0; i < 2; i++) {
            int q   = tid + i * 256;
            int row = q >> 3;
            int kq  = (q & 7) * 4;
            *(float4*)&Bs[row][kq] =
                *(const float4*)(W + (size_t)(j0 + row) * 512 + k0 + kq);
        }
        __syncthreads();

#pragma unroll
        for (int kk = 0; kk < 32; kk += 4) {
            ulonglong2 a2[8], b2[4];
#pragma unroll
            for (int i = 0; i < 8; i++)
                a2[i] = *(const ulonglong2*)&As[tm * 8 + i][kk];
#pragma unroll
            for (int j = 0; j < 4; j++)
                b2[j] = *(const ulonglong2*)&Bs[tn * 4 + j][kk];
#pragma unroll
            for (int i = 0; i < 8; i++)
#pragma unroll
                for (int j = 0; j < 4; j++) {
                    ffma2(acc[i][j], a2[i].x, b2[j].x);
                    ffma2(acc[i][j], a2[i].y, b2[j].y);
                }
        }
        __syncthreads();
    }

    float4 bb4 = *(const float4*)(bias + j0 + tn * 4);
#pragma unroll
    for (int i = 0; i < 8; i++) {
        int m = m0 + tm * 8 + i;
        int t = m >> 6;
        int b = m & 63;
        float4 o;
        o.x = hsum2(acc[i][0]) + bb4.x;
        o.y = hsum2(acc[i][1]) + bb4.y;
        o.z = hsum2(acc[i][2]) + bb4.z;
        o.w = hsum2(acc[i][3]) + bb4.w;
        *(float4*)(&g_pre[d][t][b][j0 + tn * 4]) = o;
    }
}

// ---------------- persistent HMMA recurrence ----------------------------------
// 128 CTAs (1/SM), 256 threads (8 warps). CTA = (d, 8 n-values).
// Output cols c = nl*4 + gate (gate-interleaved). M=64 batch, N=32, K=512.
// Split-bf16 3-pass: acc = Hhi*Whi + Hhi*Wlo + Hlo*Whi.
__global__ __launch_bounds__(256, 1) void persist_k(const float* __restrict__ Whf,
                                                    const float* __restrict__ Whb,
                                                    const float* __restrict__ enc_c,
                                                    float* __restrict__ out) {
    extern __shared__ char sm[];
    const uint32_t sb = (uint32_t)__cvta_generic_to_shared(sm);
    __nv_bfloat16* Wh_s = (__nv_bfloat16*)(sm + SM_WH);
    __nv_bfloat16* Wl_s = (__nv_bfloat16*)(sm + SM_WL);

    const int d   = blockIdx.x >> 6;
    const int n0  = (blockIdx.x & 63) * 8;
    const int tid = threadIdx.x;
    const int w   = tid >> 5;               // warp 0..7
    const int l   = tid & 31;
    const float* __restrict__ W = d ? Whb : Whf;

    unsigned* cnt  = &g_cnt[d * 32];
    unsigned* flag = &g_flag[d * 32];
    unsigned  base = 0;
    if (tid == 0) base = *flag;

    // ---- convert resident W tile to split bf16 in smem (rows c = nl*4+gate) --
    for (int i = tid; i < 32 * 512; i += 256) {
        int r = i >> 9;                      // col index c
        int k = i & 511;
        int j = (r & 3) * 512 + n0 + (r >> 2);
        __nv_bfloat16 h, lo;
        split_bf16(W[(size_t)j * 512 + k], h, lo);
        Wh_s[r * HB + k] = h;
        Wl_s[r * HB + k] = lo;
    }

    // ---- per-lane geometry ----
    const int m0 = (w & 3) * 16;             // batch stripe
    const int jb = (w >> 2) * 16;            // col base (2 n8 tiles)
    // ldmatrix lane addresses (byte offsets in smem)
    const uint32_t aoff = (uint32_t)(((m0 + (l & 15)) * HB + ((l >> 4) * 8)) * 2);
    const uint32_t boff = (uint32_t)(((jb + ((l >> 4) & 1) * 8 + (l & 7)) * HB
                                      + (((l >> 3) & 1) * 8)) * 2);
    const uint32_t aHb = sb + SM_HH + aoff;
    const uint32_t aLb = sb + SM_HL + aoff;
    const uint32_t bHb = sb + SM_WH + boff;
    const uint32_t bLb = sb + SM_WL + boff;

    // output ownership: b_out fixed; 2 outputs (tiles), nl = nlb + 2*tile
    const int b_out = m0 + (l >> 2) + ((l & 1) ? 8 : 0);
    const int nlb   = (jb >> 2) + ((l & 2) >> 1);

    float c_reg[2];
#pragma unroll
    for (int t2 = 0; t2 < 2; t2++)
        c_reg[t2] = enc_c[b_out * 1024 + d * 512 + n0 + nlb + 2 * t2];

    __syncthreads();

    for (int t = 0; t < 512; t++) {
        const int ph = t & 1;

        // ---- stage h hi+lo (64 x 512 bf16 each) via cp.async ----
#pragma unroll
        for (int i = 0; i < 32; i++) {
            int q   = tid + i * 256;           // 0..8191
            int arr = q >> 12;                 // 0: hi, 1: lo
            int rem = q & 4095;
            int b   = rem >> 6;
            int kc  = (rem & 63) * 8;
            const void* src = arr ? (const void*)&g_hl[ph][d][b][kc]
                                  : (const void*)&g_hh[ph][d][b][kc];
            uint32_t dst = sb + (arr ? SM_HL : SM_HH) + (uint32_t)((b * HB + kc) * 2);
            cp_async16(dst, src);
        }
        cp_commit();

        // ---- epilogue operand prefetch ----
        float pre_r[2][4];
#pragma unroll
        for (int t2 = 0; t2 < 2; t2++)
#pragma unroll
            for (int g = 0; g < 4; g++)
                pre_r[t2][g] = __ldcs(&g_pre[d][t][b_out][g * 512 + n0 + nlb + 2 * t2]);

        cp_wait0();
        __syncthreads();

        // ---- HMMA k-loop: 32 k16 steps x (4 ldsm.x4 + 6 mma) ----
        float acc0[4] = {0.f, 0.f, 0.f, 0.f};
        float acc1[4] = {0.f, 0.f, 0.f, 0.f};
#pragma unroll 4
        for (int kk = 0; kk < 512; kk += 16) {
            uint32_t ah[4], al[4], bh[4], bl[4];
            ldsm4(ah, aHb + kk * 2);
            ldsm4(bh, bHb + kk * 2);
            ldsm4(al, aLb + kk * 2);
            ldsm4(bl, bLb + kk * 2);
            mma16816(acc0, ah, bh[0], bh[1]);
            mma16816(acc1, ah, bh[2], bh[3]);
            mma16816(acc0, ah, bl[0], bl[1]);
            mma16816(acc1, ah, bl[2], bl[3]);
            mma16816(acc0, al, bh[0], bh[1]);
            mma16816(acc1, al, bh[2], bh[3]);
        }

        // ---- gate exchange: pair (even,odd) swap so each lane owns 4 gates --
        const int odd = l & 1;
        const int tout = d ? (511 - t) : t;
        float* accs[2] = {acc0, acc1};
#pragma unroll
        for (int t2 = 0; t2 < 2; t2++) {
            float* a = accs[t2];
            float r0 = __shfl_xor_sync(0xFFFFFFFFu, odd ? a[0] : a[2], 1);
            float r1 = __shfl_xor_sync(0xFFFFFFFFu, odd ? a[1] : a[3], 1);
            float g0 = odd ? r0 : a[0];
            float g1 = odd ? r1 : a[1];
            float g2 = odd ? a[2] : r0;
            float g3 = odd ? a[3] : r1;

            float gi = pre_r[t2][0] + g0;
            float gf = pre_r[t2][1] + g1;
            float gg = pre_r[t2][2] + g2;
            float go = pre_r[t2][3] + g3;
            float si = sigmoid_fast(gi);
            float sf = sigmoid_fast(gf);
            float tg = tanh_fast(gg);
            float so = sigmoid_fast(go);
            float c  = sf * c_reg[t2] + si * tg;
            float h  = so * tanh_fast(c);
            c_reg[t2] = c;

            const int n = n0 + nlb + 2 * t2;
            __nv_bfloat16 hh, hl;
            split_bf16(h, hh, hl);
            g_hh[ph ^ 1][d][b_out][n] = hh;
            g_hl[ph ^ 1][d][b_out][n] = hl;
            __stcs(&out[((size_t)b_out * 512 + tout) * 1024 + d * 512 + n], h);
            if (t == 511) {
                __stcs(&out[33554432 + b_out * 1024 + d * 512 + n], h);
                __stcs(&out[33554432 + 65536 + b_out * 1024 + d * 512 + n], c);
            }
        }

        // ---- per-direction barrier (monotonic epochs) ----
        if (t < 511) {
            __threadfence();
            __syncthreads();
            if (tid == 0) {
                unsigned target = base + (unsigned)(t + 1);
                unsigned ticket = atomicAdd(cnt, 1u);
                if ((ticket & 63u) == 63u) {
                    st_rel(flag, target);
                } else {
                    while (ld_acq(flag) < target) __nanosleep(64);
                }
            }
            __syncthreads();
        }
    }
}

// ---------------- launch -----------------------------------------------------
extern "C" void kernel_launch(void* const* d_in, const int* in_sizes, int n_in,
                              void* d_out, int out_size) {
    const float* x     = (const float*)d_in[0];
    const float* enc_h = (const float*)d_in[1];
    const float* enc_c = (const float*)d_in[2];
    const float* Wih_f = (const float*)d_in[3];
    const float* Whh_f = (const float*)d_in[4];
    const float* b_f   = (const float*)d_in[5];
    const float* Wih_b = (const float*)d_in[6];
    const float* Whh_b = (const float*)d_in[7];
    const float* b_b   = (const float*)d_in[8];
    float* out = (float*)d_out;

    cudaFuncSetAttribute(persist_k, cudaFuncAttributeMaxDynamicSharedMemorySize,
                         PERSIST_SMEM);

    dummy_k<<<1, 32>>>();                  // slot alignment: slot5 = persist_k
    init_k<<<256, 256>>>(enc_h);

    dim3 gA(32, 256, 2);
    pre_k<<<gA, 256>>>(x, Wih_f, b_f, Wih_b, b_b);

    persist_k<<<NCTA, 256, PERSIST_SMEM>>>(Whh_f, Whh_b, enc_c, out);
}